// round 17
// baseline (speedup 1.0000x reference)
#include <cuda_runtime.h>
#include <cuda_bf16.h>
#include <cstdint>

#define NUM_NODES 10000
#define N_EDGES   640000
#define D         128
#define BUCKET    128
#define OVF_MAX   4096
#define NB_FUSE   256   // leading blocks of k_scatfuse that do weight fusion

// ---------------- device scratch ----------------
__device__ float d_S[NUM_NODES * D];
__device__ float d_A[NUM_NODES * D];
__device__ int   d_cur[NUM_NODES];           // zero at load; re-zeroed by k_gemm each run
__device__ float d_degf[NUM_NODES];
__device__ int2  d_perm2[NUM_NODES * BUCKET];
__device__ int3  d_ovf[OVF_MAX];
__device__ int   d_ovf_cnt;                  // zero at load; re-zeroed by k_gemm each run
__device__ __nv_bfloat16 d_MThi[128 * 512];
__device__ __nv_bfloat16 d_MTlo[128 * 512];
__device__ float d_cvec[D];

// ---------------- helpers ----------------
__device__ __forceinline__ int load_idx(const void* ei, int which, int e, int is64) {
    if (is64) {
        const long long* p = (const long long*)ei;
        return (int)__ldg(p + (size_t)which * N_EDGES + e);
    } else {
        const int* p = (const int*)ei;
        return __ldg(p + (size_t)which * N_EDGES + e);
    }
}
__device__ __forceinline__ float4 ldg4(const float* p)  { return __ldg((const float4*)p); }
__device__ __forceinline__ float4 ldcs4(const float* p) { return __ldcs((const float4*)p); }

__device__ __forceinline__ uint32_t smem_u32(const void* p) {
    uint32_t a;
    asm("{ .reg .u64 t; cvta.to.shared.u64 t, %1; cvt.u32.u64 %0, t; }" : "=r"(a) : "l"(p));
    return a;
}

__device__ __forceinline__ void split2(float a, float b, uint32_t& hi, uint32_t& lo) {
    __nv_bfloat162 h = __floats2bfloat162_rn(a, b);
    float2 hf = __bfloat1622float2(h);
    __nv_bfloat162 l = __floats2bfloat162_rn(a - hf.x, b - hf.y);
    hi = *reinterpret_cast<uint32_t*>(&h);
    lo = *reinterpret_cast<uint32_t*>(&l);
}

__device__ __forceinline__ void ldm_x4(uint32_t& r0, uint32_t& r1, uint32_t& r2, uint32_t& r3,
                                       uint32_t addr) {
    asm volatile("ldmatrix.sync.aligned.m8n8.x4.shared.b16 {%0,%1,%2,%3}, [%4];"
                 : "=r"(r0), "=r"(r1), "=r"(r2), "=r"(r3) : "r"(addr));
}
__device__ __forceinline__ void mma16816(float* c,
                                         uint32_t a0, uint32_t a1, uint32_t a2, uint32_t a3,
                                         uint32_t b0, uint32_t b1) {
    asm volatile(
        "mma.sync.aligned.m16n8k16.row.col.f32.bf16.bf16.f32 "
        "{%0,%1,%2,%3}, {%4,%5,%6,%7}, {%8,%9}, {%0,%1,%2,%3};"
        : "+f"(c[0]), "+f"(c[1]), "+f"(c[2]), "+f"(c[3])
        : "r"(a0), "r"(a1), "r"(a2), "r"(a3), "r"(b0), "r"(b1));
}
__device__ __forceinline__ void cp_async16(uint32_t smem_dst, const void* gptr) {
    asm volatile("cp.async.cg.shared.global [%0], [%1], 16;"
                 :: "r"(smem_dst), "l"(gptr) : "memory");
}

// ---------------- K0: fused scatter (ILP-2) + weight fusion ----------------
// Blocks [0, NB_FUSE): weight fusion, 2 k-rows per block.
// Blocks [NB_FUSE, ...): bucket scatter, 2 edges per thread, independent atomic chains.
__global__ void __launch_bounds__(256)
k_scatfuse(const float* __restrict__ W1,
           const float* __restrict__ b1,
           const float* __restrict__ W2,
           const void* ei) {
    int b = blockIdx.x;
    int tid = threadIdx.x;

    if (b < NB_FUSE) {
        __shared__ float rowbuf[2][D];
        int half = tid >> 7;
        int o = tid & 127;
        int r = b * 2 + half;
        bool is_copy = (r >= 256 && r < 384);
        int w1row = (r < 128) ? r : (r < 256) ? (256 + (r - 128)) : (128 + (r - 384));
        rowbuf[half][o] = is_copy ? 0.f : W1[w1row * D + o];
        __syncthreads();
        float v;
        if (is_copy) {
            v = W2[(128 + (r - 256)) * D + o];
        } else {
            float acc = 0.f;
#pragma unroll 8
            for (int h = 0; h < D; h++) acc += rowbuf[half][h] * __ldg(W2 + h * D + o);
            v = acc;
        }
        __nv_bfloat16 hi = __float2bfloat16_rn(v);
        d_MThi[o * 512 + r] = hi;
        d_MTlo[o * 512 + r] = __float2bfloat16_rn(v - __bfloat162float(hi));

        if (b == 0) {
            __syncthreads();
            if (half == 0) rowbuf[0][o] = b1[o];
            __syncthreads();
            if (half == 0) {
                float c = 0.f;
#pragma unroll 8
                for (int h = 0; h < D; h++) c += rowbuf[0][h] * __ldg(W2 + h * D + o);
                d_cvec[o] = c;
            }
        }
        return;
    }

    // dtype probe (int64 indices < 10000 -> high words all zero)
    int w = ((const int*)ei)[2 * tid + 1];
    int any = __syncthreads_or(w != 0);
    int is64 = (any == 0) ? 1 : 0;

    // 2 edges per thread: batched loads, then independent atomic+store chains
    int base = (b - NB_FUSE) * 512 + tid;
    int e0 = base, e1 = base + 256;
    int dst0 = -1, dst1 = -1, src0 = 0, src1 = 0;
    if (e0 < N_EDGES) { dst0 = load_idx(ei, 1, e0, is64); src0 = load_idx(ei, 0, e0, is64); }
    if (e1 < N_EDGES) { dst1 = load_idx(ei, 1, e1, is64); src1 = load_idx(ei, 0, e1, is64); }

    int pos0 = (dst0 >= 0) ? atomicAdd(&d_cur[dst0], 1) : 0;
    int pos1 = (dst1 >= 0) ? atomicAdd(&d_cur[dst1], 1) : 0;

    if (dst0 >= 0) {
        if (pos0 < BUCKET) d_perm2[(dst0 << 7) + pos0] = make_int2(e0, src0);
        else { int o = atomicAdd(&d_ovf_cnt, 1); if (o < OVF_MAX) d_ovf[o] = make_int3(dst0, e0, src0); }
    }
    if (dst1 >= 0) {
        if (pos1 < BUCKET) d_perm2[(dst1 << 7) + pos1] = make_int2(e1, src1);
        else { int o = atomicAdd(&d_ovf_cnt, 1); if (o < OVF_MAX) d_ovf[o] = make_int3(dst1, e1, src1); }
    }
}

// ---------------- K1: segment sums (R10/R15 known-good) ----------------
__global__ void k_agg(const float* __restrict__ x, const float* __restrict__ ea) {
    int n = blockIdx.x * 4 + (threadIdx.x >> 5);
    if (n >= NUM_NODES) return;
    int lane = threadIdx.x & 31;
    int deg = d_cur[n];
    if (lane == 0) d_degf[n] = (float)deg;
    int cnt = min(deg, BUCKET);
    const int2* bucket = d_perm2 + ((size_t)n << 7);

    float4 aS = make_float4(0.f, 0.f, 0.f, 0.f);
    float4 aA = make_float4(0.f, 0.f, 0.f, 0.f);

    int j = 0;
    for (; j + 4 <= cnt; j += 4) {
        int2 p0 = __ldg(bucket + j + 0);
        int2 p1 = __ldg(bucket + j + 1);
        int2 p2 = __ldg(bucket + j + 2);
        int2 p3 = __ldg(bucket + j + 3);
        float4 x0 = ldg4(x + (size_t)p0.y * D + lane * 4);
        float4 x1 = ldg4(x + (size_t)p1.y * D + lane * 4);
        float4 x2 = ldg4(x + (size_t)p2.y * D + lane * 4);
        float4 x3 = ldg4(x + (size_t)p3.y * D + lane * 4);
        float4 a0 = ldcs4(ea + (size_t)p0.x * D + lane * 4);
        float4 a1 = ldcs4(ea + (size_t)p1.x * D + lane * 4);
        float4 a2 = ldcs4(ea + (size_t)p2.x * D + lane * 4);
        float4 a3 = ldcs4(ea + (size_t)p3.x * D + lane * 4);
        aS.x += (x0.x + x1.x) + (x2.x + x3.x);
        aS.y += (x0.y + x1.y) + (x2.y + x3.y);
        aS.z += (x0.z + x1.z) + (x2.z + x3.z);
        aS.w += (x0.w + x1.w) + (x2.w + x3.w);
        aA.x += (a0.x + a1.x) + (a2.x + a3.x);
        aA.y += (a0.y + a1.y) + (a2.y + a3.y);
        aA.z += (a0.z + a1.z) + (a2.z + a3.z);
        aA.w += (a0.w + a1.w) + (a2.w + a3.w);
    }
    for (; j < cnt; j++) {
        int2 p = __ldg(bucket + j);
        float4 xv = ldg4(x + (size_t)p.y * D + lane * 4);
        float4 av = ldcs4(ea + (size_t)p.x * D + lane * 4);
        aS.x += xv.x; aS.y += xv.y; aS.z += xv.z; aS.w += xv.w;
        aA.x += av.x; aA.y += av.y; aA.z += av.z; aA.w += av.w;
    }

    if (deg > BUCKET) {
        int cnt_o = d_ovf_cnt;
        if (cnt_o > OVF_MAX) cnt_o = OVF_MAX;
        for (int i = 0; i < cnt_o; i++) {
            int3 v = d_ovf[i];
            if (v.x == n) {
                float4 xv = ldg4(x + (size_t)v.z * D + lane * 4);
                float4 av = ldg4(ea + (size_t)v.y * D + lane * 4);
                aS.x += xv.x; aS.y += xv.y; aS.z += xv.z; aS.w += xv.w;
                aA.x += av.x; aA.y += av.y; aA.z += av.z; aA.w += av.w;
            }
        }
    }

    *(float4*)(d_S + (size_t)n * D + lane * 4) = aS;
    *(float4*)(d_A + (size_t)n * D + lane * 4) = aA;
}

// ---------------- K2: warp-MMA GEMM + cp.async B staging + counter re-zero ----------------
#define AROWB 144
#define ABUF  (64 * AROWB)
#define BBUF  (64 * AROWB)
__global__ void __launch_bounds__(256)
k_gemm_mma(const float* __restrict__ x,
           const float* __restrict__ b2,
           float* __restrict__ out) {
    extern __shared__ __align__(16) char sm[];
    char* Ahi = sm;
    char* Alo = sm + ABUF;
    char* Bhi = sm + 2 * ABUF;
    char* Blo = sm + 2 * ABUF + BBUF;
    uint32_t AhiU = smem_u32(Ahi), AloU = smem_u32(Alo);
    uint32_t BhiU = smem_u32(Bhi), BloU = smem_u32(Blo);

    int t = threadIdx.x;
    int wid = t >> 5, lane = t & 31;
    int wm = wid & 3, wn = wid >> 2;
    int n0 = blockIdx.x * 64;
    int obase = blockIdx.y * 64;

    // self-clean counters for the NEXT kernel_launch invocation
    {
        int bid = blockIdx.x + gridDim.x * blockIdx.y;   // 0..313
        if (t < 32) {
            int i = bid * 32 + t;
            if (i < NUM_NODES) d_cur[i] = 0;
        }
        if (bid == 0 && t == 32) d_ovf_cnt = 0;
    }

    int sub = lane >> 3, lr = lane & 7;
    uint32_t a_row = wm * 16 + ((sub & 1) << 3) + lr;
    uint32_t a_col = (uint32_t)((sub >> 1) << 4);
    uint32_t a_off = a_row * AROWB + a_col;
    uint32_t b_row = ((sub >> 1) << 3) + lr;
    uint32_t b_col = (uint32_t)((sub & 1) << 4);

    float acc[4][4];
#pragma unroll
    for (int i = 0; i < 4; i++)
#pragma unroll
        for (int j = 0; j < 4; j++) acc[i][j] = 0.f;

    for (int c = 0; c < 8; c++) {
        int k0 = c * 64;
        int region = k0 >> 7;
        int kloc = k0 & 127;
        const float* base = (region == 0) ? d_S : (region == 1) ? d_A : x;

        // B tiles via cp.async (no register round-trip; overlaps A convert below)
#pragma unroll
        for (int i = 0; i < 2; i++) {
            int id = t * 2 + i;
            int row = id >> 3, q = id & 7;
            cp_async16(BhiU + row * AROWB + q * 16, d_MThi + (obase + row) * 512 + k0 + q * 8);
            cp_async16(BloU + row * AROWB + q * 16, d_MTlo + (obase + row) * 512 + k0 + q * 8);
        }
        asm volatile("cp.async.commit_group;" ::: "memory");

        // A tile: load fp32, split hi/lo, store to smem
#pragma unroll
        for (int i = 0; i < 4; i++) {
            int id = t * 4 + i;
            int row = id >> 4, seg = id & 15;
            int nn = n0 + row;
            float4 v = make_float4(0.f, 0.f, 0.f, 0.f);
            if (nn < NUM_NODES) {
                v = ldg4(base + (size_t)nn * D + kloc + seg * 4);
                if (region == 3) {
                    float dg = d_degf[nn];
                    v.x *= dg; v.y *= dg; v.z *= dg; v.w *= dg;
                }
            }
            uint2 HI, LO;
            split2(v.x, v.y, HI.x, LO.x);
            split2(v.z, v.w, HI.y, LO.y);
            *(uint2*)(Ahi + row * AROWB + seg * 8) = HI;
            *(uint2*)(Alo + row * AROWB + seg * 8) = LO;
        }
        asm volatile("cp.async.wait_group 0;" ::: "memory");
        __syncthreads();

#pragma unroll
        for (int s = 0; s < 4; s++) {
            uint32_t ah0, ah1, ah2, ah3, al0, al1, al2, al3;
            ldm_x4(ah0, ah1, ah2, ah3, AhiU + a_off + s * 32);
            ldm_x4(al0, al1, al2, al3, AloU + a_off + s * 32);
#pragma unroll
            for (int ntp = 0; ntp < 2; ntp++) {
                uint32_t boff = (wn * 32 + ntp * 16 + b_row) * AROWB + b_col + s * 32;
                uint32_t bh0, bh1, bh2, bh3, bl0, bl1, bl2, bl3;
                ldm_x4(bh0, bh1, bh2, bh3, BhiU + boff);
                ldm_x4(bl0, bl1, bl2, bl3, BloU + boff);
                mma16816(acc[ntp * 2 + 0], ah0, ah1, ah2, ah3, bh0, bh1);
                mma16816(acc[ntp * 2 + 0], ah0, ah1, ah2, ah3, bl0, bl1);
                mma16816(acc[ntp * 2 + 0], al0, al1, al2, al3, bh0, bh1);
                mma16816(acc[ntp * 2 + 1], ah0, ah1, ah2, ah3, bh2, bh3);
                mma16816(acc[ntp * 2 + 1], ah0, ah1, ah2, ah3, bl2, bl3);
                mma16816(acc[ntp * 2 + 1], al0, al1, al2, al3, bh2, bh3);
            }
        }
        __syncthreads();
    }

    int gid = lane >> 2, tig = lane & 3;
    int row0 = n0 + wm * 16 + gid;
    int row1 = row0 + 8;
    float dg0 = (row0 < NUM_NODES) ? d_degf[row0] : 0.f;
    float dg1 = (row1 < NUM_NODES) ? d_degf[row1] : 0.f;
#pragma unroll
    for (int nt = 0; nt < 4; nt++) {
        int col = obase + wn * 32 + nt * 8 + tig * 2;
        float c0 = d_cvec[col], c1 = d_cvec[col + 1];
        float z0 = b2[col], z1 = b2[col + 1];
        if (row0 < NUM_NODES) {
            float2 v = make_float2(acc[nt][0] + dg0 * c0 + z0,
                                   acc[nt][1] + dg0 * c1 + z1);
            *(float2*)(out + (size_t)row0 * D + col) = v;
        }
        if (row1 < NUM_NODES) {
            float2 v = make_float2(acc[nt][2] + dg1 * c0 + z0,
                                   acc[nt][3] + dg1 * c1 + z1);
            *(float2*)(out + (size_t)row1 * D + col) = v;
        }
    }
}

// ---------------- launch ----------------
extern "C" void kernel_launch(void* const* d_in, const int* in_sizes, int n_in,
                              void* d_out, int out_size) {
    const float* x  = (const float*)d_in[0];
    const void*  ei = d_in[1];
    const float* ea = (const float*)d_in[2];
    const float* W1 = (const float*)d_in[3];
    const float* b1 = (const float*)d_in[4];
    const float* W2 = (const float*)d_in[5];
    const float* b2 = (const float*)d_in[6];
    float* out = (float*)d_out;

    const int SMEM = 2 * ABUF + 2 * BBUF;   // 36864 B
    static bool attr_set = false;
    if (!attr_set) {
        cudaFuncSetAttribute(k_gemm_mma, cudaFuncAttributeMaxDynamicSharedMemorySize, SMEM);
        attr_set = true;
    }

    k_scatfuse<<<NB_FUSE + (N_EDGES + 511) / 512, 256>>>(W1, b1, W2, ei);
    k_agg<<<(NUM_NODES + 3) / 4, 128>>>(x, ea);
    dim3 gg((NUM_NODES + 63) / 64, 2);
    k_gemm_mma<<<gg, 256, SMEM>>>(x, b2, out);
}